// round 11
// baseline (speedup 1.0000x reference)
#include <cuda_runtime.h>

// SplineInter: 2M points, bicubic B-spline on padded 1028x1028 fp32 grid.
// R6: warp-cooperative gather — 16 lanes per point, 2 points per warp per
// LDG.32 instruction. The 4 lanes of each stencil row are consecutive
// addresses in the SAME instruction -> coalesce to ~1 L1 line, cutting
// L1tex wavefronts from ~8/point to ~4.4/point (the measured bottleneck).
// Per-lane weight = its cubic piece (poly coeffs selected once by lane id);
// 4-level shfl_xor butterfly reduces over the 16-lane group.

#define NPTS   2097152
#define I1     1028            // row stride of padded grid (floats)
#define SCALE  1024.0f
#define U      8               // point-pairs per warp iteration (16 pts/warp)

__global__ __launch_bounds__(256) void spline_kernel(
    const float2* __restrict__ x,      // [N] point pairs
    const float*  __restrict__ coeffs, // [1028*1028]
    float*        __restrict__ out)    // [N]
{
    const int tid  = blockIdx.x * blockDim.x + threadIdx.x;
    const int warp = tid >> 5;
    const int lane = tid & 31;
    const int base = warp * (2 * U);   // 16 points handled by this warp

    const int h = lane >> 4;          // which point of the pair (0/1)
    const int j = (lane >> 2) & 3;    // stencil row offset
    const int k = lane & 3;           // stencil col offset

    // Per-lane cubic-piece coefficients (w = ((A3*t+A2)*t+A1)*t+A0):
    //  piece 0: (1-t)^3          = -t^3+3t^2-3t+1
    //  piece 1: (3t-6)t^2+4      =  3t^3-6t^2   +4
    //  piece 2: -(3t+3)(t-1)^2+4 = -3t^3+3t^2+3t+1
    //  piece 3: t^3
    const float A3 = (j==0) ? -1.f : (j==1) ?  3.f : (j==2) ? -3.f : 1.f;
    const float A2 = (j==0) ?  3.f : (j==1) ? -6.f : (j==2) ?  3.f : 0.f;
    const float A1 = (j==0) ? -3.f : (j==1) ?  0.f : (j==2) ?  3.f : 0.f;
    const float A0 = (j==0) ?  1.f : (j==1) ?  4.f : (j==2) ?  1.f : 0.f;
    const float B3 = (k==0) ? -1.f : (k==1) ?  3.f : (k==2) ? -3.f : 1.f;
    const float B2 = (k==0) ?  3.f : (k==1) ? -6.f : (k==2) ?  3.f : 0.f;
    const float B1 = (k==0) ? -3.f : (k==1) ?  0.f : (k==2) ?  3.f : 0.f;
    const float B0 = (k==0) ?  1.f : (k==1) ?  4.f : (k==2) ?  1.f : 0.f;

    // Lanes 0..15 load the warp's 16 query points (one 128B line).
    float2 p = make_float2(0.f, 0.f);
    if (lane < 16) p = x[base + lane];

    float cc[U];   // gathered stencil element per pair
    float ww[U];   // this lane's weight per pair

    const int rowoff = j * I1 + k;

#pragma unroll
    for (int i = 0; i < U; i++) {
        int src  = 2 * i + h;                       // source lane for my point
        float px = __shfl_sync(0xffffffffu, p.x, src);
        float py = __shfl_sync(0xffffffffu, p.y, src);

        float xn0 = px * SCALE - 0.5f;
        float xn1 = py * SCALE - 0.5f;
        bool valid = (xn0 > -2.0f) & (xn0 < 1024.0f) &
                     (xn1 > -2.0f) & (xn1 < 1024.0f);

        float f0 = floorf(xn0);
        float f1 = floorf(xn1);
        float t0 = xn0 - f0;
        float t1 = xn1 - f1;
        int P0 = (int)f0;
        int P1 = (int)f1;

        // stencil element (row P0+1+j, col P1+1+k); clamp for safety
        int addr = (P0 + 1) * I1 + (P1 + 1) + rowoff;
        addr = min(max(addr, 0), I1 * I1 - 1);
        cc[i] = __ldg(coeffs + addr);

        float wA = fmaf(fmaf(fmaf(A3, t0, A2), t0, A1), t0, A0);
        float wB = fmaf(fmaf(fmaf(B3, t1, B2), t1, B1), t1, B0);
        float w  = wA * wB;
        ww[i] = valid ? w : 0.0f;     // invalid -> exact 0 contribution
    }

#pragma unroll
    for (int i = 0; i < U; i++) {
        float v = cc[i] * ww[i];
        // butterfly sum over the 16-lane group
        v += __shfl_xor_sync(0xffffffffu, v, 1);
        v += __shfl_xor_sync(0xffffffffu, v, 2);
        v += __shfl_xor_sync(0xffffffffu, v, 4);
        v += __shfl_xor_sync(0xffffffffu, v, 8);
        if ((lane & 15) == 0)
            out[base + 2 * i + h] = v;
    }
}

extern "C" void kernel_launch(void* const* d_in, const int* in_sizes, int n_in,
                              void* d_out, int out_size) {
    const float2* x      = (const float2*)d_in[0];
    const float*  coeffs = (const float*)d_in[1];
    float*        out    = (float*)d_out;

    const int threads = 256;                       // 8 warps/block
    const int blocks  = NPTS / (threads / 32 * 2 * U);  // 16384
    spline_kernel<<<blocks, threads>>>(x, coeffs, out);
}

// round 12
// speedup vs baseline: 1.0134x; 1.0134x over previous
#include <cuda_runtime.h>
#include <cuda_fp16.h>

// SplineInter: 2M points, bicubic B-spline on padded 1028x1028 grid.
// R11: gather in fp16. Prologue kernel quantizes coeffs (fp32->fp16) into a
// static __device__ buffer; main kernel gathers 2x LDG.64 per stencil row
// (8 lane-slots/pt vs 16) -- L1 cost tracks lane-gather slots (R0/R5/R6
// evidence), and fp16 halves the L2 sector footprint. Weight math in fp32.

#define NPTS   2097152
#define I1     1028
#define NG     (I1 * I1)       // 1056784
#define SCALE  1024.0f

__device__ __half g_h[NG];     // 2.1 MB fp16 coefficient grid (static scratch)

__global__ __launch_bounds__(256) void convert_kernel(const float* __restrict__ c) {
    int i = (blockIdx.x * blockDim.x + threadIdx.x) * 4;
    if (i + 3 < NG) {
        float4 v = *(const float4*)(c + i);
        __half2* o = (__half2*)(g_h + i);
        o[0] = __floats2half2_rn(v.x, v.y);
        o[1] = __floats2half2_rn(v.z, v.w);
    } else if (i < NG) {
        for (int k = i; k < NG; k++) g_h[k] = __float2half_rn(c[k]);
    }
}

__device__ __forceinline__ void bspline_w(float t, float w[4]) {
    float omt = 1.0f - t;
    float t2  = t * t;
    w[0] = omt * omt * omt;
    w[1] = (3.0f * t - 6.0f) * t2 + 4.0f;
    w[2] = -(3.0f * t + 3.0f) * (omt * omt) + 4.0f;
    w[3] = t * t2;
}

struct PtSetup {
    int   base;    // half-index of (row r, col c0)
    float wv[7];   // shifted col weights (7 wide)
    float w0[4];   // row weights
    bool  valid;
};

__device__ __forceinline__ PtSetup setup_point(float px, float py) {
    PtSetup s;
    float xn0 = px * SCALE - 0.5f;
    float xn1 = py * SCALE - 0.5f;
    s.valid = (xn0 > -2.0f) & (xn0 < 1024.0f) & (xn1 > -2.0f) & (xn1 < 1024.0f);

    float f0 = floorf(xn0);
    float f1 = floorf(xn1);
    float t0 = xn0 - f0;
    float t1 = xn1 - f1;
    int P0 = min(max((int)f0, -1), 1023);   // clamp => all loads in-bounds
    int P1 = min(max((int)f1, -1), 1023);

    float w1[4];
    bspline_w(t0, s.w0);
    bspline_w(t1, w1);

    int r  = P0 + 1;           // rows r..r+3 in [0,1027]
    int c  = P1 + 1;           // cols c..c+3, c in [0,1024]
    int c0 = c & ~3;
    int ko = c - c0;
    s.base = r * I1 + c0;

    bool k0 = (ko == 0), k1 = (ko == 1), k2 = (ko == 2), k3 = (ko == 3);
    s.wv[0] = k0 ? w1[0] : 0.0f;
    s.wv[1] = k0 ? w1[1] : (k1 ? w1[0] : 0.0f);
    s.wv[2] = k0 ? w1[2] : (k1 ? w1[1] : (k2 ? w1[0] : 0.0f));
    s.wv[3] = k0 ? w1[3] : (k1 ? w1[2] : (k2 ? w1[1] : w1[0]));
    s.wv[4] = k1 ? w1[3] : (k2 ? w1[2] : (k3 ? w1[1] : 0.0f));
    s.wv[5] = k2 ? w1[3] : (k3 ? w1[2] : 0.0f);
    s.wv[6] = k3 ? w1[3] : 0.0f;
    return s;
}

__device__ __forceinline__ float eval_point(const PtSetup& s,
                                            const uint2 a[4], const uint2 b[4]) {
    float acc = 0.0f;
#pragma unroll
    for (int j = 0; j < 4; j++) {
        float2 c01 = __half22float2(*(const __half2*)&a[j].x);
        float2 c23 = __half22float2(*(const __half2*)&a[j].y);
        float2 c45 = __half22float2(*(const __half2*)&b[j].x);
        float  c6  = __low2float(*(const __half2*)&b[j].y);
        float v;
        v = c01.x * s.wv[0];
        v = fmaf(c01.y, s.wv[1], v);
        v = fmaf(c23.x, s.wv[2], v);
        v = fmaf(c23.y, s.wv[3], v);
        v = fmaf(c45.x, s.wv[4], v);
        v = fmaf(c45.y, s.wv[5], v);
        v = fmaf(c6,    s.wv[6], v);
        acc = fmaf(s.w0[j], v, acc);
    }
    return s.valid ? acc : 0.0f;
}

__global__ __launch_bounds__(256) void spline_kernel(
    const float4* __restrict__ x,      // [N/2] two points per float4
    float*        __restrict__ out)    // [N]
{
    int n2 = blockIdx.x * blockDim.x + threadIdx.x;   // handles points 2*n2, 2*n2+1
    float4 q = x[n2];

    PtSetup sA = setup_point(q.x, q.y);
    PtSetup sB = setup_point(q.z, q.w);

    // Batch all 16 LDG.64 gathers (8 per point) for max MLP.
    uint2 aA[4], bA[4], aB[4], bB[4];
#pragma unroll
    for (int j = 0; j < 4; j++) {
        const __half* pA = g_h + sA.base + j * I1;
        const __half* pB = g_h + sB.base + j * I1;
        aA[j] = *(const uint2*)pA;        // halves 0..3 (8B aligned)
        bA[j] = *(const uint2*)(pA + 4);  // halves 4..7
        aB[j] = *(const uint2*)pB;
        bB[j] = *(const uint2*)(pB + 4);
    }

    out[2 * n2]     = eval_point(sA, aA, bA);
    out[2 * n2 + 1] = eval_point(sB, aB, bB);
}

extern "C" void kernel_launch(void* const* d_in, const int* in_sizes, int n_in,
                              void* d_out, int out_size) {
    const float* x      = (const float*)d_in[0];
    const float* coeffs = (const float*)d_in[1];
    float*       out    = (float*)d_out;

    // Prologue: quantize coeff grid to fp16 (deterministic, every call).
    convert_kernel<<<(NG / 4 + 255) / 256, 256>>>(coeffs);

    const int threads = 256;
    const int blocks  = (NPTS / 2) / threads;   // 4096
    spline_kernel<<<blocks, threads>>>((const float4*)x, out);
}

// round 14
// speedup vs baseline: 2.2855x; 2.2552x over previous
#include <cuda_runtime.h>
#include <cuda_fp16.h>

// SplineInter: 2M points, bicubic B-spline on padded 1028x1028 fp32 grid.
// R12: patch-table. Evidence (R0/R5/R6/R11): divergent L1 cost is per
// lane-request (LDG.32=1u, LDG.128=2.4u), coalescing irrelevant. So pack the
// entire 4x4 stencil of every possible base cell into 32 contiguous fp16
// bytes (prologue), then each point needs only 2x LDG.128 (4.8u vs 16u) and
// exactly ONE 32B L2 sector (vs ~5.6). Table 1025^2*32B = 33.6MB, L2-resident.

#define NPTS   2097152
#define I1     1028            // padded grid row stride (floats)
#define TD     1025            // table dim: base (r,c) each in [0,1024]
#define SCALE  1024.0f

__device__ __half g_patch[(size_t)TD * TD * 16];   // 33.6 MB static scratch

// ---- Prologue: build per-cell 4x4 fp16 patches -------------------------
__global__ __launch_bounds__(256) void build_patch(const float* __restrict__ c) {
    int idx = blockIdx.x * blockDim.x + threadIdx.x;
    if (idx >= TD * TD) return;
    int r  = idx / TD;
    int cc = idx - r * TD;
    const float* src = c + r * I1 + cc;

    __half2 h[8];
#pragma unroll
    for (int j = 0; j < 4; j++) {
        const float* row = src + j * I1;
        h[2 * j]     = __floats2half2_rn(row[0], row[1]);
        h[2 * j + 1] = __floats2half2_rn(row[2], row[3]);
    }
    uint4* dst = (uint4*)(g_patch + (size_t)idx * 16);
    dst[0] = *(const uint4*)&h[0];
    dst[1] = *(const uint4*)&h[4];
}

// ---- Main kernel --------------------------------------------------------
__device__ __forceinline__ void bspline_w(float t, float w[4]) {
    float omt = 1.0f - t;
    float t2  = t * t;
    w[0] = omt * omt * omt;
    w[1] = (3.0f * t - 6.0f) * t2 + 4.0f;
    w[2] = -(3.0f * t + 3.0f) * (omt * omt) + 4.0f;
    w[3] = t * t2;
}

__device__ __forceinline__ float rowdot(unsigned lo, unsigned hi, const float wB[4]) {
    float2 a = __half22float2(*(const __half2*)&lo);
    float2 b = __half22float2(*(const __half2*)&hi);
    float s = a.x * wB[0];
    s = fmaf(a.y, wB[1], s);
    s = fmaf(b.x, wB[2], s);
    s = fmaf(b.y, wB[3], s);
    return s;
}

__global__ __launch_bounds__(256) void spline_kernel(
    const float2* __restrict__ x,      // [N]
    float*        __restrict__ out)    // [N]
{
    int n = blockIdx.x * blockDim.x + threadIdx.x;
    float2 p = x[n];

    float xn0 = p.x * SCALE - 0.5f;
    float xn1 = p.y * SCALE - 0.5f;
    bool valid = (xn0 > -2.0f) & (xn0 < 1024.0f) &
                 (xn1 > -2.0f) & (xn1 < 1024.0f);

    float f0 = floorf(xn0);
    float f1 = floorf(xn1);
    float t0 = xn0 - f0;
    float t1 = xn1 - f1;
    int P0 = min(max((int)f0, -1), 1023);   // clamp => table index in range
    int P1 = min(max((int)f1, -1), 1023);

    float wA[4], wB[4];
    bspline_w(t0, wA);
    bspline_w(t1, wB);

    // patch base (r,c) = (P0+1, P1+1), each in [0,1024]
    int q = (P0 + 1) * TD + (P1 + 1);
    const uint4* pp = (const uint4*)(g_patch + (size_t)q * 16);
    uint4 A = __ldg(pp);       // rows 0,1 of the stencil (8 halves)
    uint4 B = __ldg(pp + 1);   // rows 2,3

    float acc;
    acc = wA[0] * rowdot(A.x, A.y, wB);
    acc = fmaf(wA[1], rowdot(A.z, A.w, wB), acc);
    acc = fmaf(wA[2], rowdot(B.x, B.y, wB), acc);
    acc = fmaf(wA[3], rowdot(B.z, B.w, wB), acc);

    out[n] = valid ? acc : 0.0f;
}

extern "C" void kernel_launch(void* const* d_in, const int* in_sizes, int n_in,
                              void* d_out, int out_size) {
    const float*  x      = (const float*)d_in[0];
    const float*  coeffs = (const float*)d_in[1];
    float*        out    = (float*)d_out;

    const int nt = 256;
    build_patch<<<(TD * TD + nt - 1) / nt, nt>>>(coeffs);
    spline_kernel<<<NPTS / nt, nt>>>((const float2*)x, out);
}